// round 1
// baseline (speedup 1.0000x reference)
#include <cuda_runtime.h>

#define HDIM   64
#define NHEADS 4
#define QKDIM  256           // NHEADS * HDIM
#define N_SRC  50000
#define N_TGT  10000
#define N_E    250000
#define N_LBL  200000

// ---------------- scratch (static device memory; no allocations) ----------------
__device__ float g_xs_a[N_SRC * HDIM];
__device__ float g_xs_b[N_SRC * HDIM];
__device__ float g_xt_a[N_TGT * HDIM];
__device__ float g_xt_b[N_TGT * HDIM];

__device__ float g_q_st[N_TGT * QKDIM];   // q of tgt nodes (st conv)
__device__ float g_k_ts[N_TGT * QKDIM];   // k of tgt nodes (ts conv)
__device__ float g_v_ts[N_TGT * QKDIM];
__device__ float g_q_ts[N_SRC * QKDIM];   // q of src nodes (ts conv)
__device__ float g_k_st[N_SRC * QKDIM];
__device__ float g_v_st[N_SRC * QKDIM];

__device__ float    g_sc_st[N_E * NHEADS];
__device__ float    g_sc_ts[N_E * NHEADS];
__device__ unsigned g_m_st[N_TGT * NHEADS];
__device__ float    g_d_st[N_TGT * NHEADS];
__device__ unsigned g_m_ts[N_SRC * NHEADS];
__device__ float    g_d_ts[N_SRC * NHEADS];

// ---------------- helpers ----------------
__device__ __forceinline__ unsigned f2o(float f) {
    unsigned u = __float_as_uint(f);
    return (u & 0x80000000u) ? ~u : (u | 0x80000000u);
}
__device__ __forceinline__ float o2f(unsigned u) {
    u = (u & 0x80000000u) ? (u & 0x7fffffffu) : ~u;
    return __uint_as_float(u);
}

// ---------------- kernels ----------------
__global__ void zero_kernel(float* __restrict__ p, int n) {
    int i = blockIdx.x * blockDim.x + threadIdx.x;
    if (i < n) p[i] = 0.0f;
}

__global__ void gather_rows(const float* __restrict__ emb, const int* __restrict__ ids,
                            float* __restrict__ out, int nrows) {
    int i = blockIdx.x * blockDim.x + threadIdx.x;
    int total = nrows * HDIM;
    if (i >= total) return;
    int row = i >> 6, d = i & 63;
    out[i] = emb[(size_t)ids[row] * HDIM + d];
}

// Fused projection GEMM: X[N,64] -> three [N,256] (q/k/v-like) + one [N,64] skip.
// Tiles: 64 rows x 64 cols, K=64 full, 256 threads, 4x4 microtile per thread.
__global__ void proj_kernel(const float* __restrict__ X, int N,
                            const float* __restrict__ W0, const float* __restrict__ W1,
                            const float* __restrict__ W2, const float* __restrict__ W3,
                            const float* __restrict__ b0, const float* __restrict__ b1,
                            const float* __restrict__ b2, const float* __restrict__ b3,
                            float* __restrict__ o0, float* __restrict__ o1,
                            float* __restrict__ o2, float* __restrict__ o3) {
    __shared__ float  As[64][65];
    __shared__ float4 Bs4[64][16];

    int cb = blockIdx.y;                 // 0..12 (13 col blocks of 64)
    const float* W; const float* bias; float* out; int wstride, ostride, lcb;
    if (cb < 4)       { W = W0; bias = b0; out = o0; wstride = 256; ostride = 256; lcb = cb; }
    else if (cb < 8)  { W = W1; bias = b1; out = o1; wstride = 256; ostride = 256; lcb = cb - 4; }
    else if (cb < 12) { W = W2; bias = b2; out = o2; wstride = 256; ostride = 256; lcb = cb - 8; }
    else              { W = W3; bias = b3; out = o3; wstride = 64;  ostride = 64;  lcb = 0; }
    int colbase = lcb * 64;
    int rowbase = blockIdx.x * 64;
    int t = threadIdx.x;

    float* Bsf = (float*)Bs4;
    #pragma unroll
    for (int idx = t; idx < 4096; idx += 256) {
        int kk = idx >> 6, c = idx & 63;
        Bsf[kk * 64 + c] = W[kk * wstride + colbase + c];
    }
    #pragma unroll
    for (int idx = t; idx < 4096; idx += 256) {
        int r = idx >> 6, kk = idx & 63;
        int gr = rowbase + r;
        As[r][kk] = (gr < N) ? X[(size_t)gr * HDIM + kk] : 0.0f;
    }
    __syncthreads();

    int tx = t & 15, ty = t >> 4;
    float4 c0 = {0,0,0,0}, c1 = {0,0,0,0}, c2 = {0,0,0,0}, c3 = {0,0,0,0};
    #pragma unroll 8
    for (int kk = 0; kk < 64; kk++) {
        float4 b = Bs4[kk][tx];
        float a0 = As[ty * 4 + 0][kk];
        float a1 = As[ty * 4 + 1][kk];
        float a2 = As[ty * 4 + 2][kk];
        float a3 = As[ty * 4 + 3][kk];
        c0.x += a0 * b.x; c0.y += a0 * b.y; c0.z += a0 * b.z; c0.w += a0 * b.w;
        c1.x += a1 * b.x; c1.y += a1 * b.y; c1.z += a1 * b.z; c1.w += a1 * b.w;
        c2.x += a2 * b.x; c2.y += a2 * b.y; c2.z += a2 * b.z; c2.w += a2 * b.w;
        c3.x += a3 * b.x; c3.y += a3 * b.y; c3.z += a3 * b.z; c3.w += a3 * b.w;
    }

    float4 bb = *(const float4*)(bias + colbase + tx * 4);
    c0.x += bb.x; c0.y += bb.y; c0.z += bb.z; c0.w += bb.w;
    c1.x += bb.x; c1.y += bb.y; c1.z += bb.z; c1.w += bb.w;
    c2.x += bb.x; c2.y += bb.y; c2.z += bb.z; c2.w += bb.w;
    c3.x += bb.x; c3.y += bb.y; c3.z += bb.z; c3.w += bb.w;

    int col = colbase + tx * 4;
    int r0 = rowbase + ty * 4;
    if (r0 + 0 < N) *(float4*)(out + (size_t)(r0 + 0) * ostride + col) = c0;
    if (r0 + 1 < N) *(float4*)(out + (size_t)(r0 + 1) * ostride + col) = c1;
    if (r0 + 2 < N) *(float4*)(out + (size_t)(r0 + 2) * ostride + col) = c2;
    if (r0 + 3 < N) *(float4*)(out + (size_t)(r0 + 3) * ostride + col) = c3;
}

// Pass A: per-edge, per-head score = dot(q[dst,h], k[src,h]) / 8; atomicMax segment max.
// One warp per edge; 8 lanes per head.
__global__ void score_kernel(const int* __restrict__ esrc, const int* __restrict__ edst,
                             const float* __restrict__ q, const float* __restrict__ k,
                             float* __restrict__ score, unsigned* __restrict__ mmax,
                             int nedge) {
    int warp = (blockIdx.x * blockDim.x + threadIdx.x) >> 5;
    if (warp >= nedge) return;
    int lane = threadIdx.x & 31;
    int s = esrc[warp], d = edst[warp];
    int h = lane >> 3, sub = lane & 7;
    const float4* qp = (const float4*)(q + (size_t)d * QKDIM + h * HDIM + sub * 8);
    const float4* kp = (const float4*)(k + (size_t)s * QKDIM + h * HDIM + sub * 8);
    float4 q0 = qp[0], q1 = qp[1];
    float4 k0 = kp[0], k1 = kp[1];
    float dot = q0.x * k0.x + q0.y * k0.y + q0.z * k0.z + q0.w * k0.w
              + q1.x * k1.x + q1.y * k1.y + q1.z * k1.z + q1.w * k1.w;
    dot += __shfl_down_sync(0xffffffffu, dot, 4, 8);
    dot += __shfl_down_sync(0xffffffffu, dot, 2, 8);
    dot += __shfl_down_sync(0xffffffffu, dot, 1, 8);
    if (sub == 0) {
        float sc = dot * 0.125f;
        score[(size_t)warp * NHEADS + h] = sc;
        atomicMax(&mmax[(size_t)d * NHEADS + h], f2o(sc));
    }
}

// Pass B: e = exp(score - m[dst]); score <- e; denom[dst] += e.
__global__ void exp_kernel(const int* __restrict__ edst, const unsigned* __restrict__ mmax,
                           float* __restrict__ score, float* __restrict__ denom, int nedge) {
    int i = blockIdx.x * blockDim.x + threadIdx.x;
    if (i >= nedge * NHEADS) return;
    int e = i >> 2, h = i & 3;
    int d = edst[e];
    float m = o2f(mmax[(size_t)d * NHEADS + h]);
    float ex = __expf(score[i] - m);
    score[i] = ex;
    atomicAdd(&denom[(size_t)d * NHEADS + h], ex);
}

// Pass C: out[dst, 0:64] += (1/4) * sum_h alpha_h * v[src, h, 0:64]. Warp per edge; lane = 2 dims.
__global__ void agg_kernel(const int* __restrict__ esrc, const int* __restrict__ edst,
                           const float* __restrict__ sc, const float* __restrict__ den,
                           const float* __restrict__ v, float* __restrict__ out, int nedge) {
    int warp = (blockIdx.x * blockDim.x + threadIdx.x) >> 5;
    if (warp >= nedge) return;
    int lane = threadIdx.x & 31;
    int s = esrc[warp], d = edst[warp];
    size_t eb = (size_t)warp * NHEADS, db = (size_t)d * NHEADS;
    float a0 = sc[eb + 0] / den[db + 0];
    float a1 = sc[eb + 1] / den[db + 1];
    float a2 = sc[eb + 2] / den[db + 2];
    float a3 = sc[eb + 3] / den[db + 3];
    const float2* vp = (const float2*)(v + (size_t)s * QKDIM);
    float2 v0 = vp[lane], v1 = vp[32 + lane], v2 = vp[64 + lane], v3 = vp[96 + lane];
    float ax = 0.25f * (a0 * v0.x + a1 * v1.x + a2 * v2.x + a3 * v3.x);
    float ay = 0.25f * (a0 * v0.y + a1 * v1.y + a2 * v2.y + a3 * v3.y);
    atomicAdd(&out[(size_t)d * HDIM + lane * 2 + 0], ax);
    atomicAdd(&out[(size_t)d * HDIM + lane * 2 + 1], ay);
}

__global__ void relu_kernel(float* __restrict__ p, int n) {
    int i = blockIdx.x * blockDim.x + threadIdx.x;
    if (i < n) p[i] = fmaxf(p[i], 0.0f);
}

// Classifier: pred[i] = dot(xs[l0[i]], xt[l1[i]]), 8 lanes per pair.
__global__ void pred_kernel(const int* __restrict__ l0, const int* __restrict__ l1,
                            const float* __restrict__ xs, const float* __restrict__ xt,
                            float* __restrict__ out, int n) {
    int gid = blockIdx.x * blockDim.x + threadIdx.x;
    int pair = gid >> 3, sub = gid & 7;
    if (pair >= n) return;
    int a = l0[pair], b = l1[pair];
    const float4* xa = (const float4*)(xs + (size_t)a * HDIM);
    const float4* xb = (const float4*)(xt + (size_t)b * HDIM);
    float4 p0 = xa[sub * 2], p1 = xa[sub * 2 + 1];
    float4 q0 = xb[sub * 2], q1 = xb[sub * 2 + 1];
    float dot = p0.x * q0.x + p0.y * q0.y + p0.z * q0.z + p0.w * q0.w
              + p1.x * q1.x + p1.y * q1.y + p1.z * q1.z + p1.w * q1.w;
    dot += __shfl_down_sync(0xffffffffu, dot, 4, 8);
    dot += __shfl_down_sync(0xffffffffu, dot, 2, 8);
    dot += __shfl_down_sync(0xffffffffu, dot, 1, 8);
    if (sub == 0) out[pair] = dot;
}

// ---------------- launch ----------------
extern "C" void kernel_launch(void* const* d_in, const int* in_sizes, int n_in,
                              void* d_out, int out_size) {
    const float* src_emb = (const float*)d_in[0];
    const float* tgt_emb = (const float*)d_in[1];
    const float* Wq = (const float*)d_in[2];
    const float* bq = (const float*)d_in[3];
    const float* Wk = (const float*)d_in[4];
    const float* bk = (const float*)d_in[5];
    const float* Wv = (const float*)d_in[6];
    const float* bv = (const float*)d_in[7];
    const float* Ws = (const float*)d_in[8];
    const float* bs = (const float*)d_in[9];
    const int* nid_s = (const int*)d_in[10];
    const int* nid_t = (const int*)d_in[11];
    const int* e_st  = (const int*)d_in[12];
    const int* e_ts  = (const int*)d_in[13];
    const int* lbl   = (const int*)d_in[14];
    float* out = (float*)d_out;

    float *xs_a, *xs_b, *xt_a, *xt_b;
    float *q_st, *k_ts, *v_ts, *q_ts, *k_st, *v_st;
    float *sc_st, *sc_ts, *d_st, *d_ts;
    unsigned *m_st, *m_ts;
    cudaGetSymbolAddress((void**)&xs_a, g_xs_a);
    cudaGetSymbolAddress((void**)&xs_b, g_xs_b);
    cudaGetSymbolAddress((void**)&xt_a, g_xt_a);
    cudaGetSymbolAddress((void**)&xt_b, g_xt_b);
    cudaGetSymbolAddress((void**)&q_st, g_q_st);
    cudaGetSymbolAddress((void**)&k_ts, g_k_ts);
    cudaGetSymbolAddress((void**)&v_ts, g_v_ts);
    cudaGetSymbolAddress((void**)&q_ts, g_q_ts);
    cudaGetSymbolAddress((void**)&k_st, g_k_st);
    cudaGetSymbolAddress((void**)&v_st, g_v_st);
    cudaGetSymbolAddress((void**)&sc_st, g_sc_st);
    cudaGetSymbolAddress((void**)&sc_ts, g_sc_ts);
    cudaGetSymbolAddress((void**)&m_st, g_m_st);
    cudaGetSymbolAddress((void**)&d_st, g_d_st);
    cudaGetSymbolAddress((void**)&m_ts, g_m_ts);
    cudaGetSymbolAddress((void**)&d_ts, g_d_ts);

    gather_rows<<<(N_SRC * HDIM + 255) / 256, 256>>>(src_emb, nid_s, xs_a, N_SRC);
    gather_rows<<<(N_TGT * HDIM + 255) / 256, 256>>>(tgt_emb, nid_t, xt_a, N_TGT);

    for (int l = 0; l < 2; l++) {
        float* in_s = l ? xs_b : xs_a;  float* out_s = l ? xs_a : xs_b;
        float* in_t = l ? xt_b : xt_a;  float* out_t = l ? xt_a : xt_b;

        zero_kernel<<<(N_TGT * NHEADS + 255) / 256, 256>>>((float*)m_st, N_TGT * NHEADS);
        zero_kernel<<<(N_TGT * NHEADS + 255) / 256, 256>>>(d_st, N_TGT * NHEADS);
        zero_kernel<<<(N_SRC * NHEADS + 255) / 256, 256>>>((float*)m_ts, N_SRC * NHEADS);
        zero_kernel<<<(N_SRC * NHEADS + 255) / 256, 256>>>(d_ts, N_SRC * NHEADS);

        dim3 gs((N_SRC + 63) / 64, 13), gt((N_TGT + 63) / 64, 13);
        // src-side projections: k_st (Wk[l,0]), v_st (Wv[l,0]), q_ts (Wq[l,1]), skip (Ws[l,1])
        proj_kernel<<<gs, 256>>>(in_s, N_SRC,
            Wk + (size_t)(l * 2 + 0) * 64 * 256, Wv + (size_t)(l * 2 + 0) * 64 * 256,
            Wq + (size_t)(l * 2 + 1) * 64 * 256, Ws + (size_t)(l * 2 + 1) * 64 * 64,
            bk + (l * 2 + 0) * 256, bv + (l * 2 + 0) * 256,
            bq + (l * 2 + 1) * 256, bs + (l * 2 + 1) * 64,
            k_st, v_st, q_ts, out_s);
        // tgt-side projections: q_st (Wq[l,0]), k_ts (Wk[l,1]), v_ts (Wv[l,1]), skip (Ws[l,0])
        proj_kernel<<<gt, 256>>>(in_t, N_TGT,
            Wq + (size_t)(l * 2 + 0) * 64 * 256, Wk + (size_t)(l * 2 + 1) * 64 * 256,
            Wv + (size_t)(l * 2 + 1) * 64 * 256, Ws + (size_t)(l * 2 + 0) * 64 * 64,
            bq + (l * 2 + 0) * 256, bk + (l * 2 + 1) * 256,
            bv + (l * 2 + 1) * 256, bs + (l * 2 + 0) * 64,
            q_st, k_ts, v_ts, out_t);

        int sb = (N_E * 32 + 255) / 256;  // one warp per edge
        score_kernel<<<sb, 256>>>(e_st, e_st + N_E, q_st, k_st, sc_st, m_st, N_E);
        score_kernel<<<sb, 256>>>(e_ts, e_ts + N_E, q_ts, k_ts, sc_ts, m_ts, N_E);

        int eb = (N_E * NHEADS + 255) / 256;
        exp_kernel<<<eb, 256>>>(e_st + N_E, m_st, sc_st, d_st, N_E);
        exp_kernel<<<eb, 256>>>(e_ts + N_E, m_ts, sc_ts, d_ts, N_E);

        agg_kernel<<<sb, 256>>>(e_st, e_st + N_E, sc_st, d_st, v_st, out_t, N_E);
        agg_kernel<<<sb, 256>>>(e_ts, e_ts + N_E, sc_ts, d_ts, v_ts, out_s, N_E);

        if (l == 0) {
            relu_kernel<<<(N_SRC * HDIM + 255) / 256, 256>>>(out_s, N_SRC * HDIM);
            relu_kernel<<<(N_TGT * HDIM + 255) / 256, 256>>>(out_t, N_TGT * HDIM);
        }
    }

    // after layer 1, final embeddings live in the *_a buffers
    pred_kernel<<<(N_LBL * 8 + 255) / 256, 256>>>(lbl, lbl + N_LBL, xs_a, xt_a, out, N_LBL);
}